// round 1
// baseline (speedup 1.0000x reference)
#include <cuda_runtime.h>
#include <cstdint>

// FASTMultiHeadAttention: Taylor-2 "fastmax" attention with RPE, causal.
// B=1, H=8, N=2048, D=64, fp32.
//
// s_ij = q_i·k_j + q_i·R[i-j],  R[t] = rpe[t + N - 1]   (causal => t >= 0)
// w    = 1 + s + s^2/2  (j<=i else 0)
// out_i = (sum_j w_ij v_j) / (sum_j w_ij)
//
// One CTA per (head, 64-row query block), streaming 64-col key blocks.
// Numerator/denominator are linear sums (no softmax max-trick needed).

namespace {
constexpr int H   = 8;
constexpr int N   = 2048;
constexpr int D   = 64;
constexpr int BI  = 64;
constexpr int BJ  = 64;
constexpr int NIB = N / BI;   // 32
constexpr int NT  = 256;      // 16x16 threads, 4x4 micro-tile each

// shared memory strides (in floats)
constexpr int QSTR = 68;    // qs[d][ii], padded (68%32==4 -> mild write conflicts only)
constexpr int KSTR = 68;    // ks[d][jj]
constexpr int RSTR = 132;   // rs[d][delta], delta in [0,128); 132*4B is 16B-multiple
constexpr int RCOLS = 128;
constexpr int WSTR = 64;    // ws[ii][jj]
constexpr int VSTR = 64;    // vs[jj][dd]

constexpr int SM_Q = 0;
constexpr int SM_K = SM_Q + D * QSTR;        // 4352
constexpr int SM_R = SM_K + D * KSTR;        // 8704
constexpr int SM_V = SM_R + D * RSTR;        // 17152
constexpr int SM_W = SM_V + BJ * VSTR;       // 21248
constexpr int SM_TOT_FLOATS = SM_W + BI * WSTR;  // 25344
constexpr int SMEM_BYTES = SM_TOT_FLOATS * 4;    // 101376 B
}  // namespace

__global__ void __launch_bounds__(NT, 1)
fastmax_attn_kernel(const float* __restrict__ q,
                    const float* __restrict__ k,
                    const float* __restrict__ v,
                    const float* __restrict__ rpe,
                    float* __restrict__ out)
{
    extern __shared__ float sm[];
    float* qs = sm + SM_Q;
    float* ks = sm + SM_K;
    float* rs = sm + SM_R;
    float* vs = sm + SM_V;
    float* ws = sm + SM_W;

    const int tid = threadIdx.x;
    const int tx  = tid & 15;   // output-col group (jj or dd)
    const int ty  = tid >> 4;   // row group (ii)

    // heaviest i-blocks first for load balance across the 148 SMs
    const int bx = blockIdx.x;
    const int h  = bx & 7;
    const int ib = (NIB - 1) - (bx >> 3);
    const int i0 = ib * BI;

    const float* qh = q + (size_t)h * N * D;
    const float* kh = k + (size_t)h * N * D;
    const float* vh = v + (size_t)h * N * D;
    float*       oh = out + (size_t)h * N * D;

    // ---- load Q tile transposed: qs[d][ii] ----
    #pragma unroll
    for (int idx = tid; idx < BI * D; idx += NT) {
        int d = idx & 63, ii = idx >> 6;
        qs[d * QSTR + ii] = qh[(size_t)(i0 + ii) * D + d];
    }

    float accO[4][4];
    float den[4];
    #pragma unroll
    for (int r = 0; r < 4; r++) {
        den[r] = 0.f;
        #pragma unroll
        for (int c = 0; c < 4; c++) accO[r][c] = 0.f;
    }

    // delta base for this thread's micro-tile diagonals:
    // needed delta = (ii - jj) + 63 = 4*(ty-tx) + 63 + (r-c), r-c in [-3,3]
    // load 8 values at dbase = 4*(ty-tx)+60 .. +67 (two aligned float4s)
    const int dbase = 4 * (ty - tx) + 60;   // in [0, 120]

    for (int jb = 0; jb <= ib; jb++) {
        const int j0 = jb * BJ;
        __syncthreads();  // prior iter's readers of ks/vs/rs done

        // ---- fill K tile transposed: ks[d][jj] ----
        #pragma unroll
        for (int idx = tid; idx < BJ * D; idx += NT) {
            int d = idx & 63, jj = idx >> 6;
            ks[d * KSTR + jj] = kh[(size_t)(j0 + jj) * D + d];
        }
        // ---- fill V tile (row-major, contiguous float4 copy) ----
        {
            const float4* src = (const float4*)(vh + (size_t)j0 * D);
            float4* dst = (float4*)vs;
            #pragma unroll
            for (int idx = tid; idx < BJ * D / 4; idx += NT) dst[idx] = src[idx];
        }
        // ---- fill R diagonal tile: rs[d][delta] = R[t], t = i0-j0-63+delta ----
        {
            const int tbase = i0 - j0 - 63;
            #pragma unroll
            for (int idx = tid; idx < RCOLS * D; idx += NT) {
                int d = idx & 63, delta = idx >> 6;
                int t = tbase + delta;
                float val = 0.f;
                if (t >= 0 && t < N) val = rpe[(size_t)(t + N - 1) * D + d];
                rs[d * RSTR + delta] = val;
            }
        }
        __syncthreads();

        // ---- S = Q K^T + Q R^T(diag) over d ----
        float sacc[4][4];
        #pragma unroll
        for (int r = 0; r < 4; r++)
            #pragma unroll
            for (int c = 0; c < 4; c++) sacc[r][c] = 0.f;

        const float* qp = qs + 4 * ty;
        const float* kp = ks + 4 * tx;
        const float* rp = rs + dbase;
        #pragma unroll 8
        for (int d = 0; d < D; d++) {
            float4 qv = *(const float4*)(qp + d * QSTR);
            float4 kv = *(const float4*)(kp + d * KSTR);
            float4 ra = *(const float4*)(rp + d * RSTR);
            float4 rb = *(const float4*)(rp + d * RSTR + 4);
            float qf[4] = {qv.x, qv.y, qv.z, qv.w};
            float kf[4] = {kv.x, kv.y, kv.z, kv.w};
            float rv[8] = {ra.x, ra.y, ra.z, ra.w, rb.x, rb.y, rb.z, rb.w};
            #pragma unroll
            for (int r = 0; r < 4; r++) {
                #pragma unroll
                for (int c = 0; c < 4; c++) {
                    sacc[r][c] = fmaf(qf[r], kf[c], sacc[r][c]);
                    sacc[r][c] = fmaf(qf[r], rv[3 + r - c], sacc[r][c]);
                }
            }
        }

        // ---- w = 1 + s + s^2/2, causal mask on diagonal tile, write ws, accum den ----
        const bool diag = (jb == ib);
        #pragma unroll
        for (int r = 0; r < 4; r++) {
            float4 wrow;
            float* wp = &wrow.x;
            #pragma unroll
            for (int c = 0; c < 4; c++) {
                float s = sacc[r][c];
                float w = fmaf(s, fmaf(s, 0.5f, 1.0f), 1.0f);
                if (diag && (4 * tx + c > 4 * ty + r)) w = 0.f;
                wp[c] = w;
                den[r] += w;
            }
            *(float4*)&ws[(4 * ty + r) * WSTR + 4 * tx] = wrow;
        }
        __syncthreads();

        // ---- accO += W * V ----
        #pragma unroll 4
        for (int jj = 0; jj < BJ; jj += 4) {
            float4 w4[4];
            #pragma unroll
            for (int r = 0; r < 4; r++)
                w4[r] = *(const float4*)&ws[(4 * ty + r) * WSTR + jj];
            #pragma unroll
            for (int u = 0; u < 4; u++) {
                float4 v4 = *(const float4*)&vs[(jj + u) * VSTR + 4 * tx];
                #pragma unroll
                for (int r = 0; r < 4; r++) {
                    float wv = ((const float*)&w4[r])[u];
                    accO[r][0] = fmaf(wv, v4.x, accO[r][0]);
                    accO[r][1] = fmaf(wv, v4.y, accO[r][1]);
                    accO[r][2] = fmaf(wv, v4.z, accO[r][2]);
                    accO[r][3] = fmaf(wv, v4.w, accO[r][3]);
                }
            }
        }
    }

    // ---- reduce den across the 16 tx lanes (stays within half-warp) ----
    #pragma unroll
    for (int r = 0; r < 4; r++) {
        float dsum = den[r];
        #pragma unroll
        for (int off = 8; off >= 1; off >>= 1)
            dsum += __shfl_xor_sync(0xffffffffu, dsum, off);
        den[r] = dsum;
    }

    // ---- write out = accO / den ----
    #pragma unroll
    for (int r = 0; r < 4; r++) {
        float inv = 1.0f / den[r];
        float4 o;
        o.x = accO[r][0] * inv;
        o.y = accO[r][1] * inv;
        o.z = accO[r][2] * inv;
        o.w = accO[r][3] * inv;
        *(float4*)&oh[(size_t)(i0 + 4 * ty + r) * D + 4 * tx] = o;
    }
}

extern "C" void kernel_launch(void* const* d_in, const int* in_sizes, int n_in,
                              void* d_out, int out_size)
{
    (void)in_sizes; (void)n_in; (void)out_size;
    const float* q   = (const float*)d_in[0];
    const float* k   = (const float*)d_in[1];
    const float* v   = (const float*)d_in[2];
    const float* rpe = (const float*)d_in[3];
    // d_in[4] is the mask flag; setup always passes 1 (causal) — baked in.
    float* out = (float*)d_out;

    cudaFuncSetAttribute(fastmax_attn_kernel,
                         cudaFuncAttributeMaxDynamicSharedMemorySize, SMEM_BYTES);
    fastmax_attn_kernel<<<H * NIB, NT, SMEM_BYTES>>>(q, k, v, rpe, out);
}

// round 3
// speedup vs baseline: 1.6314x; 1.6314x over previous
#include <cuda_runtime.h>
#include <cstdint>

// FASTMultiHeadAttention via tf32 mma.sync (m16n8k8), split-2 precision scores.
// B=1, H=8, N=2048, D=64, fp32 in/out, causal.
//
// s_ij = q_i.k_j + q_i.R[i-j],  R[t] = rpe[t+N-1]
// w = 1 + s + s^2/2 (causal), out_i = sum(w v)/sum(w)
//
// One CTA per (head, 64-row i-block); 8 warps as 4(m) x 2(n).
// Per 64-wide j-tile (iterated m = 0..ib, j0 = (ib-m)*64):
//   P-new = Q(64x64) x Rslice^T(64x64)  -> 128-slot rolling diagonal ring
//   S     = Q x K^T, s += ring gather
//   O    += W x V  (W A-frags from S accumulators via shuffles)

namespace {
constexpr int H = 8, N = 2048, D = 64;
constexpr int NIB = 32;
constexpr int NT  = 256;

constexpr int KSTR = 68;    // [row][d]; 68%32==4 -> conflict-free B-frag loads
constexpr int VSTR = 72;    // 72%32==8 -> conflict-free V-frag loads
constexpr int PSTR = 132;

constexpr int SM_KHI = 0;
constexpr int SM_KLO = SM_KHI + 64 * KSTR;
constexpr int SM_RHI = SM_KLO + 64 * KSTR;
constexpr int SM_RLO = SM_RHI + 64 * KSTR;
constexpr int SM_VHI = SM_RLO + 64 * KSTR;
constexpr int SM_VLO = SM_VHI + 64 * VSTR;
constexpr int SM_PS  = SM_VLO + 64 * VSTR;
constexpr int SM_TOT = SM_PS + 64 * PSTR;      // 35072 floats
constexpr int SMEM_BYTES = SM_TOT * 4;         // 140288 B
}  // namespace

__device__ __forceinline__ void mma8(float* c, const uint32_t* a, uint32_t b0, uint32_t b1)
{
    asm volatile(
        "mma.sync.aligned.m16n8k8.row.col.f32.tf32.tf32.f32 "
        "{%0,%1,%2,%3}, {%4,%5,%6,%7}, {%8,%9}, {%0,%1,%2,%3};"
        : "+f"(c[0]), "+f"(c[1]), "+f"(c[2]), "+f"(c[3])
        : "r"(a[0]), "r"(a[1]), "r"(a[2]), "r"(a[3]), "r"(b0), "r"(b1));
}

__device__ __forceinline__ void split_tf32(float x, uint32_t& h, uint32_t& l)
{
    asm("cvt.rna.tf32.f32 %0, %1;" : "=r"(h) : "f"(x));
    float r = x - __uint_as_float(h);
    asm("cvt.rna.tf32.f32 %0, %1;" : "=r"(l) : "f"(r));
}

__global__ void __launch_bounds__(NT, 1)
fastmax_mma_kernel(const float* __restrict__ q,
                   const float* __restrict__ k,
                   const float* __restrict__ v,
                   const float* __restrict__ rpe,
                   float* __restrict__ out)
{
    extern __shared__ float sm[];
    float* skhi = sm + SM_KHI;
    float* sklo = sm + SM_KLO;
    float* srhi = sm + SM_RHI;
    float* srlo = sm + SM_RLO;
    float* svhi = sm + SM_VHI;
    float* svlo = sm + SM_VLO;
    float* sps  = sm + SM_PS;

    const int tid  = threadIdx.x;
    const int lane = tid & 31;
    const int wid  = tid >> 5;
    const int g    = lane >> 2;   // 0..7
    const int t4   = lane & 3;    // 0..3
    const int wm   = wid & 3;     // 4 row-warps (16 rows each)
    const int wn   = wid >> 2;    // 2 col-warps (32 j-cols each)

    const int bx = blockIdx.x;
    const int h  = bx & 7;
    const int ib = (NIB - 1) - (bx >> 3);   // heaviest i-blocks first
    const int i0 = ib * 64;

    const float* qp = q   + (size_t)h * N * D;
    const float* kp = k   + (size_t)h * N * D;
    const float* vp = v   + (size_t)h * N * D;
    float*       op = out + (size_t)h * N * D;

    // ---- stage Q (coalesced), then build persistent A fragments (hi/lo) ----
    for (int idx = tid; idx < 64 * 64; idx += NT) {
        int r = idx >> 6, d = idx & 63;
        skhi[r * KSTR + d] = qp[(size_t)(i0 + r) * D + d];
    }
    __syncthreads();

    const int prow0 = 16 * wm + g;
    uint32_t qfh[8][4], qfl[8][4];
    #pragma unroll
    for (int kk = 0; kk < 8; kk++) {
        split_tf32(skhi[prow0 * KSTR + 8 * kk + t4],           qfh[kk][0], qfl[kk][0]);
        split_tf32(skhi[(prow0 + 8) * KSTR + 8 * kk + t4],     qfh[kk][1], qfl[kk][1]);
        split_tf32(skhi[prow0 * KSTR + 8 * kk + t4 + 4],       qfh[kk][2], qfl[kk][2]);
        split_tf32(skhi[(prow0 + 8) * KSTR + 8 * kk + t4 + 4], qfh[kk][3], qfl[kk][3]);
    }

    float oacc[8][4];
    #pragma unroll
    for (int nt = 0; nt < 8; nt++)
        #pragma unroll
        for (int c = 0; c < 4; c++) oacc[nt][c] = 0.f;
    float den0 = 0.f, den1 = 0.f;

    float* psrow0 = sps + prow0 * PSTR;
    float* psrow1 = sps + (prow0 + 8) * PSTR;

    for (int m = 0; m <= ib; m++) {
        const int j0 = (ib - m) * 64;
        __syncthreads();   // prior-iter consumers (and Q-frag reads) done

        // ---- fill K/V/R tiles, split into tf32 hi/lo ----
        for (int idx = tid; idx < 4096; idx += NT) {
            int r = idx >> 6, d = idx & 63;
            uint32_t hh, ll;
            split_tf32(kp[(size_t)(j0 + r) * D + d], hh, ll);
            skhi[r * KSTR + d] = __uint_as_float(hh);
            sklo[r * KSTR + d] = __uint_as_float(ll);
            split_tf32(vp[(size_t)(j0 + r) * D + d], hh, ll);
            svhi[r * VSTR + d] = __uint_as_float(hh);
            svlo[r * VSTR + d] = __uint_as_float(ll);
            // new diagonal deltas: t = 64m + r, always valid (<= i0+63 <= N-1)
            split_tf32(rpe[(size_t)(64 * m + r + N - 1) * D + d], hh, ll);
            srhi[r * KSTR + d] = __uint_as_float(hh);
            srlo[r * KSTR + d] = __uint_as_float(ll);
        }
        __syncthreads();

        // ---- P-new = Q x Rslice^T (split-2: hh + lh + hl) ----
        {
            float pacc[4][4];
            #pragma unroll
            for (int nt = 0; nt < 4; nt++)
                #pragma unroll
                for (int c = 0; c < 4; c++) pacc[nt][c] = 0.f;
            #pragma unroll
            for (int kk = 0; kk < 8; kk++) {
                #pragma unroll
                for (int nt = 0; nt < 4; nt++) {
                    int col = 32 * wn + 8 * nt + g;
                    uint32_t bh0 = __float_as_uint(srhi[col * KSTR + 8 * kk + t4]);
                    uint32_t bh1 = __float_as_uint(srhi[col * KSTR + 8 * kk + t4 + 4]);
                    uint32_t bl0 = __float_as_uint(srlo[col * KSTR + 8 * kk + t4]);
                    uint32_t bl1 = __float_as_uint(srlo[col * KSTR + 8 * kk + t4 + 4]);
                    mma8(pacc[nt], qfh[kk], bh0, bh1);
                    mma8(pacc[nt], qfl[kk], bh0, bh1);
                    mma8(pacc[nt], qfh[kk], bl0, bl1);
                }
            }
            const int bslot = (64 * m) & 127;
            #pragma unroll
            for (int nt = 0; nt < 4; nt++) {
                int dl = 32 * wn + 8 * nt + 2 * t4;
                *(float2*)&psrow0[bslot + dl] = make_float2(pacc[nt][0], pacc[nt][1]);
                *(float2*)&psrow1[bslot + dl] = make_float2(pacc[nt][2], pacc[nt][3]);
            }
        }
        __syncthreads();   // new P half visible

        // ---- S = Q x K^T ----
        float sacc[4][4];
        #pragma unroll
        for (int nt = 0; nt < 4; nt++)
            #pragma unroll
            for (int c = 0; c < 4; c++) sacc[nt][c] = 0.f;
        #pragma unroll
        for (int kk = 0; kk < 8; kk++) {
            #pragma unroll
            for (int nt = 0; nt < 4; nt++) {
                int col = 32 * wn + 8 * nt + g;
                uint32_t bh0 = __float_as_uint(skhi[col * KSTR + 8 * kk + t4]);
                uint32_t bh1 = __float_as_uint(skhi[col * KSTR + 8 * kk + t4 + 4]);
                uint32_t bl0 = __float_as_uint(sklo[col * KSTR + 8 * kk + t4]);
                uint32_t bl1 = __float_as_uint(sklo[col * KSTR + 8 * kk + t4 + 4]);
                mma8(sacc[nt], qfh[kk], bh0, bh1);
                mma8(sacc[nt], qfl[kk], bh0, bh1);
                mma8(sacc[nt], qfh[kk], bl0, bl1);
            }
        }

        // ---- s += P gather; w = 1+s+s^2/2; mask; den from rounded w ----
        uint32_t wt[4][4];
        #pragma unroll
        for (int nt = 0; nt < 4; nt++) {
            int colb = 32 * wn + 8 * nt + 2 * t4;
            #pragma unroll
            for (int c = 0; c < 4; c++) {
                int row_l = prow0 + ((c >> 1) << 3);
                int col_l = colb + (c & 1);
                unsigned slot = (unsigned)(64 * m + row_l - col_l) & 127u;
                float s = sacc[nt][c] + sps[row_l * PSTR + slot];
                float w = fmaf(s, fmaf(s, 0.5f, 1.0f), 1.0f);
                if (m == 0 && col_l > row_l) w = 0.0f;   // causal (diagonal tile)
                uint32_t wu;
                asm("cvt.rna.tf32.f32 %0, %1;" : "=r"(wu) : "f"(w));
                wt[nt][c] = wu;
                if (c < 2) den0 += __uint_as_float(wu);
                else       den1 += __uint_as_float(wu);
            }
        }

        // ---- O += W x V  (A-frags from accumulators via shuffles; V split-2) ----
        #pragma unroll
        for (int kk = 0; kk < 4; kk++) {
            const int src = 4 * g + (t4 >> 1);
            uint32_t v00  = __shfl_sync(0xffffffffu, wt[kk][0], src);
            uint32_t v01  = __shfl_sync(0xffffffffu, wt[kk][1], src);
            uint32_t v20  = __shfl_sync(0xffffffffu, wt[kk][2], src);
            uint32_t v21  = __shfl_sync(0xffffffffu, wt[kk][3], src);
            uint32_t v00b = __shfl_sync(0xffffffffu, wt[kk][0], src + 2);
            uint32_t v01b = __shfl_sync(0xffffffffu, wt[kk][1], src + 2);
            uint32_t v20b = __shfl_sync(0xffffffffu, wt[kk][2], src + 2);
            uint32_t v21b = __shfl_sync(0xffffffffu, wt[kk][3], src + 2);
            uint32_t a[4];
            const bool odd = (t4 & 1);
            a[0] = odd ? v01  : v00;
            a[1] = odd ? v21  : v20;
            a[2] = odd ? v01b : v00b;
            a[3] = odd ? v21b : v20b;
            const int jrow = 32 * wn + 8 * kk + t4;
            #pragma unroll
            for (int nt = 0; nt < 8; nt++) {
                int dcol = 8 * nt + g;
                uint32_t bh0 = __float_as_uint(svhi[jrow * VSTR + dcol]);
                uint32_t bh1 = __float_as_uint(svhi[(jrow + 4) * VSTR + dcol]);
                uint32_t bl0 = __float_as_uint(svlo[jrow * VSTR + dcol]);
                uint32_t bl1 = __float_as_uint(svlo[(jrow + 4) * VSTR + dcol]);
                mma8(oacc[nt], a, bh0, bh1);
                mma8(oacc[nt], a, bl0, bl1);
            }
        }
    }

    // ---- epilogue ----
    den0 += __shfl_xor_sync(0xffffffffu, den0, 1);
    den0 += __shfl_xor_sync(0xffffffffu, den0, 2);
    den1 += __shfl_xor_sync(0xffffffffu, den1, 1);
    den1 += __shfl_xor_sync(0xffffffffu, den1, 2);

    __syncthreads();                 // all smem reads of last tile done
    float* ob   = sm;                // reuse K region: 64 x KSTR
    float* denb = sm + SM_RHI;       // reuse R region: 64 floats

    if (wn == 1) {
        #pragma unroll
        for (int nt = 0; nt < 8; nt++) {
            int dcol = 8 * nt + 2 * t4;
            *(float2*)&ob[prow0 * KSTR + dcol]       = make_float2(oacc[nt][0], oacc[nt][1]);
            *(float2*)&ob[(prow0 + 8) * KSTR + dcol] = make_float2(oacc[nt][2], oacc[nt][3]);
        }
        if (t4 == 0) { denb[prow0] = den0; denb[prow0 + 8] = den1; }
    }
    __syncthreads();
    if (wn == 0) {
        float inv0 = 1.0f / (den0 + denb[prow0]);
        float inv1 = 1.0f / (den1 + denb[prow0 + 8]);
        #pragma unroll
        for (int nt = 0; nt < 8; nt++) {
            int dcol = 8 * nt + 2 * t4;
            float2 p0 = *(const float2*)&ob[prow0 * KSTR + dcol];
            float2 p1 = *(const float2*)&ob[(prow0 + 8) * KSTR + dcol];
            float2 o0 = make_float2((oacc[nt][0] + p0.x) * inv0,
                                    (oacc[nt][1] + p0.y) * inv0);
            float2 o1 = make_float2((oacc[nt][2] + p1.x) * inv1,
                                    (oacc[nt][3] + p1.y) * inv1);
            *(float2*)&op[(size_t)(i0 + prow0) * D + dcol]     = o0;
            *(float2*)&op[(size_t)(i0 + prow0 + 8) * D + dcol] = o1;
        }
    }
}

extern "C" void kernel_launch(void* const* d_in, const int* in_sizes, int n_in,
                              void* d_out, int out_size)
{
    (void)in_sizes; (void)n_in; (void)out_size;
    const float* q   = (const float*)d_in[0];
    const float* k   = (const float*)d_in[1];
    const float* v   = (const float*)d_in[2];
    const float* rpe = (const float*)d_in[3];
    // d_in[4] is the mask flag; setup always passes 1 (causal) — baked in.
    float* out = (float*)d_out;

    cudaFuncSetAttribute(fastmax_mma_kernel,
                         cudaFuncAttributeMaxDynamicSharedMemorySize, SMEM_BYTES);
    fastmax_mma_kernel<<<H * NIB, NT, SMEM_BYTES>>>(q, k, v, rpe, out);
}

// round 4
// speedup vs baseline: 1.7071x; 1.0464x over previous
#include <cuda_runtime.h>
#include <cstdint>

// FASTMultiHeadAttention via tf32 mma.sync (m16n8k8), split-2 scores.
// B=1, H=8, N=2048, D=64, fp32, causal.
// R4: 512-thread CTAs (4x4 warps), prepass tf32-split of K/V/R into global
// buffers, fused S+P GEMM with Q A-frags reloaded from a packed smem buffer,
// named-barrier for P-ring visibility (ring is wm-partitioned).

namespace {
constexpr int H = 8, N = 2048, D = 64;
constexpr int NIB = 32;
constexpr int NT  = 512;

constexpr int KSTR = 68;    // 68%32==4 -> conflict-free B-frag LDS
constexpr int VSTR = 72;    // 72%32==8 -> conflict-free V-frag LDS
constexpr int PSTR = 132;

constexpr int SM_K  = 0;
constexpr int SM_KL = SM_K  + 64 * KSTR;   // 4352
constexpr int SM_R  = SM_KL + 64 * KSTR;   // 8704
constexpr int SM_RL = SM_R  + 64 * KSTR;   // 13056
constexpr int SM_V  = SM_RL + 64 * KSTR;   // 17408
constexpr int SM_VL = SM_V  + 64 * VSTR;   // 22016
constexpr int SM_PS = SM_VL + 64 * VSTR;   // 26624  (ring, also Q staging)
constexpr int SM_QP = SM_PS + 64 * PSTR;   // 35072  (Q frag pack: hi 4096 + lo 4096)
constexpr int SM_TOT = SM_QP + 8192;       // 43264 floats
constexpr int SMEM_BYTES = SM_TOT * 4;     // 173056 B
}  // namespace

// prepass outputs: tf32 hi/lo of K, V (per head) and R[t]=rpe[t+N-1] (shared)
__device__ float g_khi[H * N * D], g_klo[H * N * D];
__device__ float g_vhi[H * N * D], g_vlo[H * N * D];
__device__ float g_rhi[N * D],     g_rlo[N * D];

__device__ __forceinline__ void mma8(float* c, const uint32_t* a, uint32_t b0, uint32_t b1)
{
    asm volatile(
        "mma.sync.aligned.m16n8k8.row.col.f32.tf32.tf32.f32 "
        "{%0,%1,%2,%3}, {%4,%5,%6,%7}, {%8,%9}, {%0,%1,%2,%3};"
        : "+f"(c[0]), "+f"(c[1]), "+f"(c[2]), "+f"(c[3])
        : "r"(a[0]), "r"(a[1]), "r"(a[2]), "r"(a[3]), "r"(b0), "r"(b1));
}

__device__ __forceinline__ void split_tf32(float x, uint32_t& h, uint32_t& l)
{
    asm("cvt.rna.tf32.f32 %0, %1;" : "=r"(h) : "f"(x));
    float r = x - __uint_as_float(h);
    asm("cvt.rna.tf32.f32 %0, %1;" : "=r"(l) : "f"(r));
}

__global__ void __launch_bounds__(512, 1)
prepass_split(const float* __restrict__ k,
              const float* __restrict__ v,
              const float* __restrict__ rpe)
{
    int i = blockIdx.x * 512 + threadIdx.x;   // grid covers H*N*D exactly
    uint32_t hh, ll;
    split_tf32(k[i], hh, ll);
    g_khi[i] = __uint_as_float(hh);
    g_klo[i] = __uint_as_float(ll);
    split_tf32(v[i], hh, ll);
    g_vhi[i] = __uint_as_float(hh);
    g_vlo[i] = __uint_as_float(ll);
    if (i < N * D) {
        split_tf32(rpe[(N - 1) * D + i], hh, ll);
        g_rhi[i] = __uint_as_float(hh);
        g_rlo[i] = __uint_as_float(ll);
    }
}

__global__ void __launch_bounds__(NT, 1)
fastmax_mma_kernel(const float* __restrict__ q,
                   float* __restrict__ out)
{
    extern __shared__ float sm[];
    float* skhi = sm + SM_K;
    float* sklo = sm + SM_KL;
    float* srhi = sm + SM_R;
    float* srlo = sm + SM_RL;
    float* svhi = sm + SM_V;
    float* svlo = sm + SM_VL;
    float* sps  = sm + SM_PS;
    float4* qph = (float4*)(sm + SM_QP);
    float4* qpl = qph + 1024;

    const int tid  = threadIdx.x;
    const int lane = tid & 31;
    const int wid  = tid >> 5;
    const int g    = lane >> 2;
    const int t4   = lane & 3;
    const int wm   = wid & 3;     // 4 row-groups of 16 rows
    const int wn   = wid >> 2;    // 4 col-groups of 16 j-cols

    const int bx = blockIdx.x;
    const int h  = bx & 7;
    const int ib = (NIB - 1) - (bx >> 3);   // heaviest first
    const int i0 = ib * 64;

    const float* qp = q   + (size_t)h * N * D;
    float*       op = out + (size_t)h * N * D;
    const float* khi = g_khi + (size_t)h * N * D;
    const float* klo = g_klo + (size_t)h * N * D;
    const float* vhi = g_vhi + (size_t)h * N * D;
    const float* vlo = g_vlo + (size_t)h * N * D;

    // ---- stage raw Q (into ring area), then build A-frag pack ----
    {
        const float4* qsrc = (const float4*)(qp + (size_t)i0 * D);
        float4* sq4 = (float4*)sps;
        for (int f = tid; f < 1024; f += NT) sq4[f] = qsrc[f];
    }
    __syncthreads();
    {
        const float* sq = sps;
        for (int e = tid; e < 1024; e += NT) {
            int wmp = e >> 8, kkp = (e >> 5) & 7, lp = e & 31;
            int gp = lp >> 2, t4p = lp & 3;
            int r0 = 16 * wmp + gp;
            float x00 = sq[r0 * 64 + 8 * kkp + t4p];
            float x10 = sq[(r0 + 8) * 64 + 8 * kkp + t4p];
            float x01 = sq[r0 * 64 + 8 * kkp + t4p + 4];
            float x11 = sq[(r0 + 8) * 64 + 8 * kkp + t4p + 4];
            uint32_t h0, l0, h1, l1, h2, l2, h3, l3;
            split_tf32(x00, h0, l0);
            split_tf32(x10, h1, l1);
            split_tf32(x01, h2, l2);
            split_tf32(x11, h3, l3);
            qph[e] = make_float4(__uint_as_float(h0), __uint_as_float(h1),
                                 __uint_as_float(h2), __uint_as_float(h3));
            qpl[e] = make_float4(__uint_as_float(l0), __uint_as_float(l1),
                                 __uint_as_float(l2), __uint_as_float(l3));
        }
    }

    float oacc[8][4];
    #pragma unroll
    for (int nt = 0; nt < 8; nt++)
        #pragma unroll
        for (int c = 0; c < 4; c++) oacc[nt][c] = 0.f;
    float den0 = 0.f, den1 = 0.f;

    const int prow0 = 16 * wm + g;
    float* psrow0 = sps + prow0 * PSTR;
    float* psrow1 = sps + (prow0 + 8) * PSTR;

    for (int m = 0; m <= ib; m++) {
        const int j0 = (ib - m) * 64;
        __syncthreads();   // prior-iter consumers done (also orders qpack build)

        // ---- fill K/V/R hi+lo tiles: pure float4 copies from prepass ----
        {
            const float4* s0 = (const float4*)(khi + (size_t)j0 * D);
            const float4* s1 = (const float4*)(klo + (size_t)j0 * D);
            const float4* s2 = (const float4*)(g_rhi + (size_t)(64 * m) * D);
            const float4* s3 = (const float4*)(g_rlo + (size_t)(64 * m) * D);
            const float4* s4 = (const float4*)(vhi + (size_t)j0 * D);
            const float4* s5 = (const float4*)(vlo + (size_t)j0 * D);
            for (int f = tid; f < 1024; f += NT) {
                int r = f >> 4, c4 = (f & 15) << 2;
                float4 a0 = s0[f], a1 = s1[f], a2 = s2[f], a3 = s3[f], a4 = s4[f], a5 = s5[f];
                *(float4*)&skhi[r * KSTR + c4] = a0;
                *(float4*)&sklo[r * KSTR + c4] = a1;
                *(float4*)&srhi[r * KSTR + c4] = a2;
                *(float4*)&srlo[r * KSTR + c4] = a3;
                *(float4*)&svhi[r * VSTR + c4] = a4;
                *(float4*)&svlo[r * VSTR + c4] = a5;
            }
        }
        __syncthreads();

        // ---- fused S = Q K^T and P = Q Rslice^T (split-2: hh + lh + hl) ----
        float sacc[2][4], pacc[2][4];
        #pragma unroll
        for (int nt = 0; nt < 2; nt++)
            #pragma unroll
            for (int c = 0; c < 4; c++) { sacc[nt][c] = 0.f; pacc[nt][c] = 0.f; }

        #pragma unroll
        for (int kk = 0; kk < 8; kk++) {
            float4 qh4 = qph[(wm * 8 + kk) * 32 + lane];
            float4 ql4 = qpl[(wm * 8 + kk) * 32 + lane];
            uint32_t aH[4] = {__float_as_uint(qh4.x), __float_as_uint(qh4.y),
                              __float_as_uint(qh4.z), __float_as_uint(qh4.w)};
            uint32_t aL[4] = {__float_as_uint(ql4.x), __float_as_uint(ql4.y),
                              __float_as_uint(ql4.z), __float_as_uint(ql4.w)};
            #pragma unroll
            for (int nt = 0; nt < 2; nt++) {
                int col = 16 * wn + 8 * nt + g;
                uint32_t bh0 = __float_as_uint(skhi[col * KSTR + 8 * kk + t4]);
                uint32_t bh1 = __float_as_uint(skhi[col * KSTR + 8 * kk + t4 + 4]);
                uint32_t bl0 = __float_as_uint(sklo[col * KSTR + 8 * kk + t4]);
                uint32_t bl1 = __float_as_uint(sklo[col * KSTR + 8 * kk + t4 + 4]);
                mma8(sacc[nt], aH, bh0, bh1);
                mma8(sacc[nt], aL, bh0, bh1);
                mma8(sacc[nt], aH, bl0, bl1);
                uint32_t rh0 = __float_as_uint(srhi[col * KSTR + 8 * kk + t4]);
                uint32_t rh1 = __float_as_uint(srhi[col * KSTR + 8 * kk + t4 + 4]);
                uint32_t rl0 = __float_as_uint(srlo[col * KSTR + 8 * kk + t4]);
                uint32_t rl1 = __float_as_uint(srlo[col * KSTR + 8 * kk + t4 + 4]);
                mma8(pacc[nt], aH, rh0, rh1);
                mma8(pacc[nt], aL, rh0, rh1);
                mma8(pacc[nt], aH, rl0, rl1);
            }
        }

        // ---- store P-new into wm-partitioned ring ----
        {
            const int bslot = (64 * m) & 127;
            #pragma unroll
            for (int nt = 0; nt < 2; nt++) {
                int dl = 16 * wn + 8 * nt + 2 * t4;
                *(float2*)&psrow0[bslot + dl] = make_float2(pacc[nt][0], pacc[nt][1]);
                *(float2*)&psrow1[bslot + dl] = make_float2(pacc[nt][2], pacc[nt][3]);
            }
        }
        // ring rows [16wm,16wm+16) are produced/consumed only by the 4 warps
        // sharing this wm -> 128-thread named barrier
        asm volatile("bar.sync %0, %1;" :: "r"(1 + wm), "r"(128) : "memory");

        // ---- s += P gather; w = 1+s+s^2/2; causal mask; den from rounded w ----
        uint32_t wt[2][4];
        #pragma unroll
        for (int nt = 0; nt < 2; nt++) {
            int colb = 16 * wn + 8 * nt + 2 * t4;
            #pragma unroll
            for (int c = 0; c < 4; c++) {
                int row_l = prow0 + ((c >> 1) << 3);
                int col_l = colb + (c & 1);
                unsigned slot = (unsigned)(64 * m + row_l - col_l) & 127u;
                float s = sacc[nt][c] + sps[row_l * PSTR + slot];
                float w = fmaf(s, fmaf(s, 0.5f, 1.0f), 1.0f);
                if (m == 0 && col_l > row_l) w = 0.0f;
                uint32_t wu;
                asm("cvt.rna.tf32.f32 %0, %1;" : "=r"(wu) : "f"(w));
                wt[nt][c] = wu;
                if (c < 2) den0 += __uint_as_float(wu);
                else       den1 += __uint_as_float(wu);
            }
        }

        // ---- O += W x V (A-frags via shuffles; V split-2) ----
        #pragma unroll
        for (int kk = 0; kk < 2; kk++) {
            const int src = 4 * g + (t4 >> 1);
            uint32_t v00  = __shfl_sync(0xffffffffu, wt[kk][0], src);
            uint32_t v01  = __shfl_sync(0xffffffffu, wt[kk][1], src);
            uint32_t v20  = __shfl_sync(0xffffffffu, wt[kk][2], src);
            uint32_t v21  = __shfl_sync(0xffffffffu, wt[kk][3], src);
            uint32_t v00b = __shfl_sync(0xffffffffu, wt[kk][0], src + 2);
            uint32_t v01b = __shfl_sync(0xffffffffu, wt[kk][1], src + 2);
            uint32_t v20b = __shfl_sync(0xffffffffu, wt[kk][2], src + 2);
            uint32_t v21b = __shfl_sync(0xffffffffu, wt[kk][3], src + 2);
            uint32_t a[4];
            const bool odd = (t4 & 1);
            a[0] = odd ? v01  : v00;
            a[1] = odd ? v21  : v20;
            a[2] = odd ? v01b : v00b;
            a[3] = odd ? v21b : v20b;
            const int jrow = 16 * wn + 8 * kk + t4;
            #pragma unroll
            for (int nt = 0; nt < 8; nt++) {
                int dcol = 8 * nt + g;
                uint32_t bh0 = __float_as_uint(svhi[jrow * VSTR + dcol]);
                uint32_t bh1 = __float_as_uint(svhi[(jrow + 4) * VSTR + dcol]);
                uint32_t bl0 = __float_as_uint(svlo[jrow * VSTR + dcol]);
                uint32_t bl1 = __float_as_uint(svlo[(jrow + 4) * VSTR + dcol]);
                mma8(oacc[nt], a, bh0, bh1);
                mma8(oacc[nt], a, bl0, bl1);
            }
        }
    }

    // ---- epilogue: reduce den over t4 lanes, combine 4 wn partials ----
    den0 += __shfl_xor_sync(0xffffffffu, den0, 1);
    den0 += __shfl_xor_sync(0xffffffffu, den0, 2);
    den1 += __shfl_xor_sync(0xffffffffu, den1, 1);
    den1 += __shfl_xor_sync(0xffffffffu, den1, 2);

    __syncthreads();   // all smem reads of final tile done
    float* denb = sm + SM_KL;          // 64 x 4
    if (wn > 0) {
        float* ob = (wn == 1) ? (sm + SM_K) : (wn == 2) ? (sm + SM_R) : (sm + SM_V);
        #pragma unroll
        for (int nt = 0; nt < 8; nt++) {
            int dcol = 8 * nt + 2 * t4;
            *(float2*)&ob[prow0 * KSTR + dcol]       = make_float2(oacc[nt][0], oacc[nt][1]);
            *(float2*)&ob[(prow0 + 8) * KSTR + dcol] = make_float2(oacc[nt][2], oacc[nt][3]);
        }
        if (t4 == 0) {
            denb[prow0 * 4 + wn]       = den0;
            denb[(prow0 + 8) * 4 + wn] = den1;
        }
    }
    __syncthreads();
    if (wn == 0) {
        float d0 = den0 + denb[prow0 * 4 + 1] + denb[prow0 * 4 + 2] + denb[prow0 * 4 + 3];
        float d1 = den1 + denb[(prow0 + 8) * 4 + 1] + denb[(prow0 + 8) * 4 + 2]
                        + denb[(prow0 + 8) * 4 + 3];
        float inv0 = 1.0f / d0;
        float inv1 = 1.0f / d1;
        float* ob1 = sm + SM_K;
        float* ob2 = sm + SM_R;
        float* ob3 = sm + SM_V;
        #pragma unroll
        for (int nt = 0; nt < 8; nt++) {
            int dcol = 8 * nt + 2 * t4;
            float2 p1 = *(const float2*)&ob1[prow0 * KSTR + dcol];
            float2 p2 = *(const float2*)&ob2[prow0 * KSTR + dcol];
            float2 p3 = *(const float2*)&ob3[prow0 * KSTR + dcol];
            float2 q1 = *(const float2*)&ob1[(prow0 + 8) * KSTR + dcol];
            float2 q2 = *(const float2*)&ob2[(prow0 + 8) * KSTR + dcol];
            float2 q3 = *(const float2*)&ob3[(prow0 + 8) * KSTR + dcol];
            float2 o0 = make_float2((oacc[nt][0] + p1.x + p2.x + p3.x) * inv0,
                                    (oacc[nt][1] + p1.y + p2.y + p3.y) * inv0);
            float2 o1 = make_float2((oacc[nt][2] + q1.x + q2.x + q3.x) * inv1,
                                    (oacc[nt][3] + q1.y + q2.y + q3.y) * inv1);
            *(float2*)&op[(size_t)(i0 + prow0) * D + dcol]     = o0;
            *(float2*)&op[(size_t)(i0 + prow0 + 8) * D + dcol] = o1;
        }
    }
}

extern "C" void kernel_launch(void* const* d_in, const int* in_sizes, int n_in,
                              void* d_out, int out_size)
{
    (void)in_sizes; (void)n_in; (void)out_size;
    const float* q   = (const float*)d_in[0];
    const float* k   = (const float*)d_in[1];
    const float* v   = (const float*)d_in[2];
    const float* rpe = (const float*)d_in[3];
    float* out = (float*)d_out;

    prepass_split<<<(H * N * D) / 512, 512>>>(k, v, rpe);

    cudaFuncSetAttribute(fastmax_mma_kernel,
                         cudaFuncAttributeMaxDynamicSharedMemorySize, SMEM_BYTES);
    fastmax_mma_kernel<<<H * NIB, NT, SMEM_BYTES>>>(q, out);
}

// round 5
// speedup vs baseline: 3.1649x; 1.8540x over previous
#include <cuda_runtime.h>
#include <cuda_bf16.h>
#include <cstdint>

// FASTMultiHeadAttention R5: bf16x2 score GEMMs (m16n8k16), tf32 W*V,
// prepass packs Q/K/R/V into mma-fragment layout, cp.async double-buffered
// tile fills, paired i-blocks for perfect load balance.
// B=1, H=8, N=2048, D=64, fp32 in/out, causal.

namespace {
constexpr int H = 8, N = 2048, D = 64;
constexpr int NT = 512;            // 16 warps: 4 wm x 4 wn

// smem (floats)
constexpr int BUFSZ = 12288;       // per buffer: K 4096 | R 4096 | V 4096
constexpr int RING  = 2 * BUFSZ;   // 24576
constexpr int PSTR  = 132;
constexpr int DENB  = RING + 64 * PSTR;      // 33024
constexpr int SMEM_FLOATS = DENB + 256;      // 33280
constexpr int SMEM_BYTES  = SMEM_FLOATS * 4; // 133120
constexpr int KSTR = 68;           // epilogue scratch stride
}

// fragment-packed operands (prepass outputs)
__device__ float4 g_qpack[262144];   // (h, mtile128, c4, lane32) x {A1,A2}
__device__ float4 g_kpack[262144];   // (h, jb32, c4, col64, t4)  {b0k1,b1k1,b0k2,b1k2}
__device__ float4 g_rpack[32768];    // (db32, c4, row64, t4)
__device__ float2 g_vpack[524288];   // (h, jb32, cj8, dcol64, t4) {b0,b1} tf32

__device__ __forceinline__ void mma16(float* c, const uint32_t* a, uint32_t b0, uint32_t b1)
{
    asm volatile(
        "mma.sync.aligned.m16n8k16.row.col.f32.bf16.bf16.f32 "
        "{%0,%1,%2,%3}, {%4,%5,%6,%7}, {%8,%9}, {%0,%1,%2,%3};"
        : "+f"(c[0]), "+f"(c[1]), "+f"(c[2]), "+f"(c[3])
        : "r"(a[0]), "r"(a[1]), "r"(a[2]), "r"(a[3]), "r"(b0), "r"(b1));
}

__device__ __forceinline__ void mma8(float* c, const uint32_t* a, uint32_t b0, uint32_t b1)
{
    asm volatile(
        "mma.sync.aligned.m16n8k8.row.col.f32.tf32.tf32.f32 "
        "{%0,%1,%2,%3}, {%4,%5,%6,%7}, {%8,%9}, {%0,%1,%2,%3};"
        : "+f"(c[0]), "+f"(c[1]), "+f"(c[2]), "+f"(c[3])
        : "r"(a[0]), "r"(a[1]), "r"(a[2]), "r"(a[3]), "r"(b0), "r"(b1));
}

__device__ __forceinline__ void split_bf16(float x, uint16_t& hi, uint16_t& lo)
{
    __nv_bfloat16 b1 = __float2bfloat16_rn(x);
    float r = x - __bfloat162float(b1);
    __nv_bfloat16 b2 = __float2bfloat16_rn(r);
    hi = __bfloat16_as_ushort(b1);
    lo = __bfloat16_as_ushort(b2);
}

__device__ __forceinline__ uint32_t pk2(uint16_t lo_even, uint16_t hi_odd)
{   // bf16x2: low half = even-k element
    return ((uint32_t)hi_odd << 16) | lo_even;
}

__device__ __forceinline__ uint32_t tf32r(float x)
{
    uint32_t r; asm("cvt.rna.tf32.f32 %0, %1;" : "=r"(r) : "f"(x)); return r;
}

__device__ __forceinline__ void cp16(uint32_t s, const void* g)
{
    asm volatile("cp.async.cg.shared.global [%0], [%1], 16;" :: "r"(s), "l"(g));
}

// ---------------- prepass kernels ----------------

__global__ void pp_q(const float* __restrict__ q)
{   // 131072 threads: (h, mt128, c4, lane32)
    int idx = blockIdx.x * 256 + threadIdx.x;
    int lane = idx & 31, c = (idx >> 5) & 3, mt = (idx >> 7) & 127, h = idx >> 14;
    int g = lane >> 2, t4 = lane & 3;
    const float* qh = q + (size_t)h * N * D;
    int r0 = mt * 16 + g;
    int k0 = c * 16 + 2 * t4;
    float x[2][4];
    #pragma unroll
    for (int rr = 0; rr < 2; rr++) {
        const float* row = qh + (size_t)(r0 + 8 * rr) * D;
        x[rr][0] = row[k0];     x[rr][1] = row[k0 + 1];
        x[rr][2] = row[k0 + 8]; x[rr][3] = row[k0 + 9];
    }
    uint16_t hb[2][4], lb[2][4];
    #pragma unroll
    for (int rr = 0; rr < 2; rr++)
        #pragma unroll
        for (int e = 0; e < 4; e++) split_bf16(x[rr][e], hb[rr][e], lb[rr][e]);
    // a0=(g,2t4..+1) a1=(g+8,..) a2=(g,2t4+8..+9) a3=(g+8,..)
    float4 A1, A2;
    A1.x = __uint_as_float(pk2(hb[0][0], hb[0][1]));
    A1.y = __uint_as_float(pk2(hb[1][0], hb[1][1]));
    A1.z = __uint_as_float(pk2(hb[0][2], hb[0][3]));
    A1.w = __uint_as_float(pk2(hb[1][2], hb[1][3]));
    A2.x = __uint_as_float(pk2(lb[0][0], lb[0][1]));
    A2.y = __uint_as_float(pk2(lb[1][0], lb[1][1]));
    A2.z = __uint_as_float(pk2(lb[0][2], lb[0][3]));
    A2.w = __uint_as_float(pk2(lb[1][2], lb[1][3]));
    g_qpack[idx * 2]     = A1;
    g_qpack[idx * 2 + 1] = A2;
}

__global__ void pp_k(const float* __restrict__ k)
{   // 262144 threads: (h, jb32, c4, col64, t4)
    int idx = blockIdx.x * 256 + threadIdx.x;
    int t4 = idx & 3, col = (idx >> 2) & 63, c = (idx >> 8) & 3;
    int jb = (idx >> 10) & 31, h = idx >> 15;
    const float* row = k + ((size_t)h * N + jb * 64 + col) * D;
    int k0 = c * 16 + 2 * t4;
    float y0 = row[k0], y1 = row[k0 + 1], y2 = row[k0 + 8], y3 = row[k0 + 9];
    uint16_t h0, l0, h1, l1, h2, l2, h3, l3;
    split_bf16(y0, h0, l0); split_bf16(y1, h1, l1);
    split_bf16(y2, h2, l2); split_bf16(y3, h3, l3);
    float4 o;
    o.x = __uint_as_float(pk2(h0, h1));   // b0 of k1
    o.y = __uint_as_float(pk2(h2, h3));   // b1 of k1
    o.z = __uint_as_float(pk2(l0, l1));   // b0 of k2
    o.w = __uint_as_float(pk2(l2, l3));   // b1 of k2
    g_kpack[idx] = o;
}

__global__ void pp_r(const float* __restrict__ rpe)
{   // 32768 threads: (db32, c4, row64, t4)
    int idx = blockIdx.x * 256 + threadIdx.x;
    int t4 = idx & 3, row = (idx >> 2) & 63, c = (idx >> 8) & 3, db = idx >> 10;
    int t = db * 64 + row;                     // delta in [0, 2047]
    const float* src = rpe + (size_t)(t + N - 1) * D;
    int k0 = c * 16 + 2 * t4;
    float y0 = src[k0], y1 = src[k0 + 1], y2 = src[k0 + 8], y3 = src[k0 + 9];
    uint16_t h0, l0, h1, l1, h2, l2, h3, l3;
    split_bf16(y0, h0, l0); split_bf16(y1, h1, l1);
    split_bf16(y2, h2, l2); split_bf16(y3, h3, l3);
    float4 o;
    o.x = __uint_as_float(pk2(h0, h1));
    o.y = __uint_as_float(pk2(h2, h3));
    o.z = __uint_as_float(pk2(l0, l1));
    o.w = __uint_as_float(pk2(l2, l3));
    g_rpack[idx] = o;
}

__global__ void pp_v(const float* __restrict__ v)
{   // 524288 threads: (h, jb32, cj8, dcol64, t4)
    int idx = blockIdx.x * 256 + threadIdx.x;
    int t4 = idx & 3, dcol = (idx >> 2) & 63, cj = (idx >> 8) & 7;
    int jb = (idx >> 11) & 31, h = idx >> 16;
    const float* vh = v + (size_t)h * N * D;
    int j0 = jb * 64 + cj * 8;
    float2 o;
    o.x = __uint_as_float(tf32r(vh[(size_t)(j0 + t4) * D + dcol]));
    o.y = __uint_as_float(tf32r(vh[(size_t)(j0 + t4 + 4) * D + dcol]));
    g_vpack[idx] = o;
}

// ---------------- main kernel ----------------

__global__ void __launch_bounds__(NT, 1)
fastmax_bf16x2_kernel(float* __restrict__ out)
{
    extern __shared__ float sm[];
    uint32_t smb;
    asm("{.reg .u64 t; cvta.to.shared.u64 t, %1; cvt.u32.u64 %0, t;}"
        : "=r"(smb) : "l"(sm));

    const int tid  = threadIdx.x;
    const int lane = tid & 31;
    const int wid  = tid >> 5;
    const int g    = lane >> 2;
    const int t4   = lane & 3;
    const int wm   = wid & 3;
    const int wn   = wid >> 2;

    const int bx = blockIdx.x;       // 128 CTAs = 8 heads x 16 pairs
    const int h  = bx & 7;
    const int p  = bx >> 3;

    float* sps = sm + RING;
    const int prow0 = 16 * wm + g;
    float* psrow0 = sps + prow0 * PSTR;
    float* psrow1 = sps + (prow0 + 8) * PSTR;
    float* op = out + (size_t)h * N * D;

    #pragma unroll 1
    for (int pass = 0; pass < 2; pass++) {
        const int ib = pass ? p : 31 - p;     // pair sums to 33 tiles
        const int i0 = ib * 64;

        // Q fragments (persistent, registers)
        uint32_t qa1[4][4], qa2[4][4];
        #pragma unroll
        for (int c = 0; c < 4; c++) {
            const float4* src = &g_qpack[(((size_t)(h * 128 + ib * 4 + wm) * 4 + c) * 32 + lane) * 2];
            float4 A1 = src[0], A2 = src[1];
            qa1[c][0] = __float_as_uint(A1.x); qa1[c][1] = __float_as_uint(A1.y);
            qa1[c][2] = __float_as_uint(A1.z); qa1[c][3] = __float_as_uint(A1.w);
            qa2[c][0] = __float_as_uint(A2.x); qa2[c][1] = __float_as_uint(A2.y);
            qa2[c][2] = __float_as_uint(A2.z); qa2[c][3] = __float_as_uint(A2.w);
        }

        float oacc[8][4];
        #pragma unroll
        for (int nt = 0; nt < 8; nt++)
            #pragma unroll
            for (int c = 0; c < 4; c++) oacc[nt][c] = 0.f;
        float den0 = 0.f, den1 = 0.f;

        // prefetch tile 0 into buf 0
        {
            const float4* gk = g_kpack + (size_t)(h * 32 + ib) * 1024;
            const float4* gr = g_rpack;
            const float4* gv = ((const float4*)g_vpack) + (size_t)(h * 32 + ib) * 1024;
            for (int t = tid; t < 1024; t += NT) {
                cp16(smb + t * 16,         gk + t);
                cp16(smb + 16384 + t * 16, gr + t);
                cp16(smb + 32768 + t * 16, gv + t);
            }
            asm volatile("cp.async.commit_group;" ::: "memory");
        }

        for (int m = 0; m <= ib; m++) {
            asm volatile("cp.async.wait_group 0;" ::: "memory");
            __syncthreads();                        // buf[m&1] ready everywhere

            if (m < ib) {                           // prefetch next into other buf
                const int jb = ib - m - 1;
                const float4* gk = g_kpack + (size_t)(h * 32 + jb) * 1024;
                const float4* gr = g_rpack + (size_t)(m + 1) * 1024;
                const float4* gv = ((const float4*)g_vpack) + (size_t)(h * 32 + jb) * 1024;
                uint32_t sb = smb + ((m + 1) & 1) * (BUFSZ * 4);
                for (int t = tid; t < 1024; t += NT) {
                    cp16(sb + t * 16,         gk + t);
                    cp16(sb + 16384 + t * 16, gr + t);
                    cp16(sb + 32768 + t * 16, gv + t);
                }
                asm volatile("cp.async.commit_group;" ::: "memory");
            }

            const uint4* kb4 = (const uint4*)(sm + (m & 1) * BUFSZ);
            const uint4* rb4 = kb4 + 1024;
            const uint2* vb2 = (const uint2*)(sm + (m & 1) * BUFSZ + 8192);

            // ---- S = QK^T, P = QR^T  (bf16x2: hh + lh + hl) ----
            float sacc[2][4], pacc[2][4];
            #pragma unroll
            for (int nt = 0; nt < 2; nt++)
                #pragma unroll
                for (int c = 0; c < 4; c++) { sacc[nt][c] = 0.f; pacc[nt][c] = 0.f; }

            #pragma unroll
            for (int c = 0; c < 4; c++) {
                #pragma unroll
                for (int nt = 0; nt < 2; nt++) {
                    int fi = (c * 64 + 16 * wn + 8 * nt + g) * 4 + t4;
                    uint4 kf = kb4[fi];
                    mma16(sacc[nt], qa1[c], kf.x, kf.y);
                    mma16(sacc[nt], qa2[c], kf.x, kf.y);
                    mma16(sacc[nt], qa1[c], kf.z, kf.w);
                    uint4 rf = rb4[fi];
                    mma16(pacc[nt], qa1[c], rf.x, rf.y);
                    mma16(pacc[nt], qa2[c], rf.x, rf.y);
                    mma16(pacc[nt], qa1[c], rf.z, rf.w);
                }
            }

            // ---- P-new into wm-partitioned 128-slot ring ----
            {
                const int bslot = (64 * m) & 127;
                #pragma unroll
                for (int nt = 0; nt < 2; nt++) {
                    int dl = 16 * wn + 8 * nt + 2 * t4;
                    *(float2*)&psrow0[bslot + dl] = make_float2(pacc[nt][0], pacc[nt][1]);
                    *(float2*)&psrow1[bslot + dl] = make_float2(pacc[nt][2], pacc[nt][3]);
                }
            }
            asm volatile("bar.sync %0, %1;" :: "r"(1 + wm), "r"(128) : "memory");

            // ---- s += P gather; w = 1+s+s^2/2; causal; den from rounded w ----
            uint32_t wt[2][4];
            #pragma unroll
            for (int nt = 0; nt < 2; nt++) {
                int colb = 16 * wn + 8 * nt + 2 * t4;
                #pragma unroll
                for (int c = 0; c < 4; c++) {
                    int row_l = prow0 + ((c >> 1) << 3);
                    int col_l = colb + (c & 1);
                    unsigned slot = (unsigned)(64 * m + row_l - col_l) & 127u;
                    float s = sacc[nt][c] + sps[row_l * PSTR + slot];
                    float w = fmaf(s, fmaf(s, 0.5f, 1.0f), 1.0f);
                    if (m == 0 && col_l > row_l) w = 0.0f;
                    uint32_t wu = tf32r(w);
                    wt[nt][c] = wu;
                    if (c < 2) den0 += __uint_as_float(wu);
                    else       den1 += __uint_as_float(wu);
                }
            }

            // ---- O += W x V (A-frags via shuffles; V single tf32) ----
            #pragma unroll
            for (int kk = 0; kk < 2; kk++) {
                const int src = 4 * g + (t4 >> 1);
                uint32_t v00  = __shfl_sync(0xffffffffu, wt[kk][0], src);
                uint32_t v01  = __shfl_sync(0xffffffffu, wt[kk][1], src);
                uint32_t v20  = __shfl_sync(0xffffffffu, wt[kk][2], src);
                uint32_t v21  = __shfl_sync(0xffffffffu, wt[kk][3], src);
                uint32_t v00b = __shfl_sync(0xffffffffu, wt[kk][0], src + 2);
                uint32_t v01b = __shfl_sync(0xffffffffu, wt[kk][1], src + 2);
                uint32_t v20b = __shfl_sync(0xffffffffu, wt[kk][2], src + 2);
                uint32_t v21b = __shfl_sync(0xffffffffu, wt[kk][3], src + 2);
                uint32_t a[4];
                const bool odd = (t4 & 1);
                a[0] = odd ? v01  : v00;
                a[1] = odd ? v21  : v20;
                a[2] = odd ? v01b : v00b;
                a[3] = odd ? v21b : v20b;
                const int cj = 2 * wn + kk;
                #pragma unroll
                for (int nt = 0; nt < 8; nt++) {
                    uint2 vf = vb2[(cj * 64 + 8 * nt + g) * 4 + t4];
                    mma8(oacc[nt], a, vf.x, vf.y);
                }
            }
        }

        // ---- epilogue: den lane-reduce, combine 4 wn partials, write ----
        den0 += __shfl_xor_sync(0xffffffffu, den0, 1);
        den0 += __shfl_xor_sync(0xffffffffu, den0, 2);
        den1 += __shfl_xor_sync(0xffffffffu, den1, 1);
        den1 += __shfl_xor_sync(0xffffffffu, den1, 2);

        __syncthreads();                 // all smem reads of final tile done
        float* ob1  = sm;                // scratch over buffer region
        float* ob2  = sm + 4352;
        float* ob3  = sm + 8704;
        float* denb = sm + DENB;

        if (wn > 0) {
            float* ob = (wn == 1) ? ob1 : (wn == 2) ? ob2 : ob3;
            #pragma unroll
            for (int nt = 0; nt < 8; nt++) {
                int dcol = 8 * nt + 2 * t4;
                *(float2*)&ob[prow0 * KSTR + dcol]       = make_float2(oacc[nt][0], oacc[nt][1]);
                *(float2*)&ob[(prow0 + 8) * KSTR + dcol] = make_float2(oacc[nt][2], oacc[nt][3]);
            }
            if (t4 == 0) {
                denb[prow0 * 4 + wn]       = den0;
                denb[(prow0 + 8) * 4 + wn] = den1;
            }
        }
        __syncthreads();
        if (wn == 0) {
            float d0 = den0 + denb[prow0 * 4 + 1] + denb[prow0 * 4 + 2] + denb[prow0 * 4 + 3];
            float d1 = den1 + denb[(prow0 + 8) * 4 + 1] + denb[(prow0 + 8) * 4 + 2]
                            + denb[(prow0 + 8) * 4 + 3];
            float inv0 = 1.0f / d0;
            float inv1 = 1.0f / d1;
            #pragma unroll
            for (int nt = 0; nt < 8; nt++) {
                int dcol = 8 * nt + 2 * t4;
                float2 p1 = *(const float2*)&ob1[prow0 * KSTR + dcol];
                float2 p2 = *(const float2*)&ob2[prow0 * KSTR + dcol];
                float2 p3 = *(const float2*)&ob3[prow0 * KSTR + dcol];
                float2 q1 = *(const float2*)&ob1[(prow0 + 8) * KSTR + dcol];
                float2 q2 = *(const float2*)&ob2[(prow0 + 8) * KSTR + dcol];
                float2 q3 = *(const float2*)&ob3[(prow0 + 8) * KSTR + dcol];
                float2 o0 = make_float2((oacc[nt][0] + p1.x + p2.x + p3.x) * inv0,
                                        (oacc[nt][1] + p1.y + p2.y + p3.y) * inv0);
                float2 o1 = make_float2((oacc[nt][2] + q1.x + q2.x + q3.x) * inv1,
                                        (oacc[nt][3] + q1.y + q2.y + q3.y) * inv1);
                *(float2*)&op[(size_t)(i0 + prow0) * D + dcol]     = o0;
                *(float2*)&op[(size_t)(i0 + prow0 + 8) * D + dcol] = o1;
            }
        }
        __syncthreads();                 // scratch free before next pass prefetch
    }
}

extern "C" void kernel_launch(void* const* d_in, const int* in_sizes, int n_in,
                              void* d_out, int out_size)
{
    (void)in_sizes; (void)n_in; (void)out_size;
    const float* q   = (const float*)d_in[0];
    const float* k   = (const float*)d_in[1];
    const float* v   = (const float*)d_in[2];
    const float* rpe = (const float*)d_in[3];
    float* out = (float*)d_out;

    pp_q<<<512, 256>>>(q);
    pp_k<<<1024, 256>>>(k);
    pp_r<<<128, 256>>>(rpe);
    pp_v<<<2048, 256>>>(v);

    cudaFuncSetAttribute(fastmax_bf16x2_kernel,
                         cudaFuncAttributeMaxDynamicSharedMemorySize, SMEM_BYTES);
    fastmax_bf16x2_kernel<<<128, NT, SMEM_BYTES>>>(out);
}

// round 6
// speedup vs baseline: 3.5425x; 1.1193x over previous
#include <cuda_runtime.h>
#include <cuda_bf16.h>
#include <cstdint>

// FASTMultiHeadAttention R6: R5 core (bf16x2 score GEMMs m16n8k16, tf32 W*V,
// fragment-packed prepass, cp.async double-buffered fills) with:
//   - all four prepass kernels fused into ONE launch (blockIdx-partitioned)
//   - 144-CTA balanced schedule: ib 28..31 solo, (p, 27-p) pairs = 29 tiles
// B=1, H=8, N=2048, D=64, fp32 in/out, causal.

namespace {
constexpr int H = 8, N = 2048, D = 64;
constexpr int NT = 512;            // 16 warps: 4 wm x 4 wn

// smem (floats)
constexpr int BUFSZ = 12288;       // per buffer: K 4096 | R 4096 | V 4096
constexpr int RING  = 2 * BUFSZ;   // 24576
constexpr int PSTR  = 132;
constexpr int DENB  = RING + 64 * PSTR;      // 33024
constexpr int SMEM_FLOATS = DENB + 256;      // 33280
constexpr int SMEM_BYTES  = SMEM_FLOATS * 4; // 133120
constexpr int KSTR = 68;           // epilogue scratch stride
}

// fragment-packed operands (prepass outputs)
__device__ float4 g_qpack[262144];   // (h, mtile128, c4, lane32) x {A1,A2}
__device__ float4 g_kpack[262144];   // (h, jb32, c4, col64, t4)  {b0k1,b1k1,b0k2,b1k2}
__device__ float4 g_rpack[32768];    // (db32, c4, row64, t4)
__device__ float2 g_vpack[524288];   // (h, jb32, cj8, dcol64, t4) {b0,b1} tf32

__device__ __forceinline__ void mma16(float* c, const uint32_t* a, uint32_t b0, uint32_t b1)
{
    asm volatile(
        "mma.sync.aligned.m16n8k16.row.col.f32.bf16.bf16.f32 "
        "{%0,%1,%2,%3}, {%4,%5,%6,%7}, {%8,%9}, {%0,%1,%2,%3};"
        : "+f"(c[0]), "+f"(c[1]), "+f"(c[2]), "+f"(c[3])
        : "r"(a[0]), "r"(a[1]), "r"(a[2]), "r"(a[3]), "r"(b0), "r"(b1));
}

__device__ __forceinline__ void mma8(float* c, const uint32_t* a, uint32_t b0, uint32_t b1)
{
    asm volatile(
        "mma.sync.aligned.m16n8k8.row.col.f32.tf32.tf32.f32 "
        "{%0,%1,%2,%3}, {%4,%5,%6,%7}, {%8,%9}, {%0,%1,%2,%3};"
        : "+f"(c[0]), "+f"(c[1]), "+f"(c[2]), "+f"(c[3])
        : "r"(a[0]), "r"(a[1]), "r"(a[2]), "r"(a[3]), "r"(b0), "r"(b1));
}

__device__ __forceinline__ void split_bf16(float x, uint16_t& hi, uint16_t& lo)
{
    __nv_bfloat16 b1 = __float2bfloat16_rn(x);
    float r = x - __bfloat162float(b1);
    __nv_bfloat16 b2 = __float2bfloat16_rn(r);
    hi = __bfloat16_as_ushort(b1);
    lo = __bfloat16_as_ushort(b2);
}

__device__ __forceinline__ uint32_t pk2(uint16_t lo_even, uint16_t hi_odd)
{   // bf16x2: low half = even-k element
    return ((uint32_t)hi_odd << 16) | lo_even;
}

__device__ __forceinline__ uint32_t tf32r(float x)
{
    uint32_t r; asm("cvt.rna.tf32.f32 %0, %1;" : "=r"(r) : "f"(x)); return r;
}

__device__ __forceinline__ void cp16(uint32_t s, const void* g)
{
    asm volatile("cp.async.cg.shared.global [%0], [%1], 16;" :: "r"(s), "l"(g));
}

// ---------------- fused prepass: 3712 blocks x 256 ----------------
//   blocks [0,512)     : Q pack   (131072 threads)
//   blocks [512,1536)  : K pack   (262144 threads)
//   blocks [1536,1664) : R pack   (32768 threads)
//   blocks [1664,3712) : V pack   (524288 threads)

__global__ void __launch_bounds__(256)
pp_fused(const float* __restrict__ q, const float* __restrict__ k,
         const float* __restrict__ v, const float* __restrict__ rpe)
{
    const int bid = blockIdx.x;
    if (bid < 512) {
        int idx = bid * 256 + threadIdx.x;
        int lane = idx & 31, c = (idx >> 5) & 3, mt = (idx >> 7) & 127, h = idx >> 14;
        int g = lane >> 2, t4 = lane & 3;
        const float* qh = q + (size_t)h * N * D;
        int r0 = mt * 16 + g;
        int k0 = c * 16 + 2 * t4;
        float x[2][4];
        #pragma unroll
        for (int rr = 0; rr < 2; rr++) {
            const float* row = qh + (size_t)(r0 + 8 * rr) * D;
            x[rr][0] = row[k0];     x[rr][1] = row[k0 + 1];
            x[rr][2] = row[k0 + 8]; x[rr][3] = row[k0 + 9];
        }
        uint16_t hb[2][4], lb[2][4];
        #pragma unroll
        for (int rr = 0; rr < 2; rr++)
            #pragma unroll
            for (int e = 0; e < 4; e++) split_bf16(x[rr][e], hb[rr][e], lb[rr][e]);
        float4 A1, A2;
        A1.x = __uint_as_float(pk2(hb[0][0], hb[0][1]));
        A1.y = __uint_as_float(pk2(hb[1][0], hb[1][1]));
        A1.z = __uint_as_float(pk2(hb[0][2], hb[0][3]));
        A1.w = __uint_as_float(pk2(hb[1][2], hb[1][3]));
        A2.x = __uint_as_float(pk2(lb[0][0], lb[0][1]));
        A2.y = __uint_as_float(pk2(lb[1][0], lb[1][1]));
        A2.z = __uint_as_float(pk2(lb[0][2], lb[0][3]));
        A2.w = __uint_as_float(pk2(lb[1][2], lb[1][3]));
        g_qpack[idx * 2]     = A1;
        g_qpack[idx * 2 + 1] = A2;
    } else if (bid < 1536) {
        int idx = (bid - 512) * 256 + threadIdx.x;
        int t4 = idx & 3, col = (idx >> 2) & 63, c = (idx >> 8) & 3;
        int jb = (idx >> 10) & 31, h = idx >> 15;
        const float* row = k + ((size_t)h * N + jb * 64 + col) * D;
        int k0 = c * 16 + 2 * t4;
        float y0 = row[k0], y1 = row[k0 + 1], y2 = row[k0 + 8], y3 = row[k0 + 9];
        uint16_t h0, l0, h1, l1, h2, l2, h3, l3;
        split_bf16(y0, h0, l0); split_bf16(y1, h1, l1);
        split_bf16(y2, h2, l2); split_bf16(y3, h3, l3);
        float4 o;
        o.x = __uint_as_float(pk2(h0, h1));
        o.y = __uint_as_float(pk2(h2, h3));
        o.z = __uint_as_float(pk2(l0, l1));
        o.w = __uint_as_float(pk2(l2, l3));
        g_kpack[idx] = o;
    } else if (bid < 1664) {
        int idx = (bid - 1536) * 256 + threadIdx.x;
        int t4 = idx & 3, row = (idx >> 2) & 63, c = (idx >> 8) & 3, db = idx >> 10;
        int t = db * 64 + row;
        const float* src = rpe + (size_t)(t + N - 1) * D;
        int k0 = c * 16 + 2 * t4;
        float y0 = src[k0], y1 = src[k0 + 1], y2 = src[k0 + 8], y3 = src[k0 + 9];
        uint16_t h0, l0, h1, l1, h2, l2, h3, l3;
        split_bf16(y0, h0, l0); split_bf16(y1, h1, l1);
        split_bf16(y2, h2, l2); split_bf16(y3, h3, l3);
        float4 o;
        o.x = __uint_as_float(pk2(h0, h1));
        o.y = __uint_as_float(pk2(h2, h3));
        o.z = __uint_as_float(pk2(l0, l1));
        o.w = __uint_as_float(pk2(l2, l3));
        g_rpack[idx] = o;
    } else {
        int idx = (bid - 1664) * 256 + threadIdx.x;
        int t4 = idx & 3, dcol = (idx >> 2) & 63, cj = (idx >> 8) & 7;
        int jb = (idx >> 11) & 31, h = idx >> 16;
        const float* vh = v + (size_t)h * N * D;
        int j0 = jb * 64 + cj * 8;
        float2 o;
        o.x = __uint_as_float(tf32r(vh[(size_t)(j0 + t4) * D + dcol]));
        o.y = __uint_as_float(tf32r(vh[(size_t)(j0 + t4 + 4) * D + dcol]));
        g_vpack[idx] = o;
    }
}

// ---------------- main kernel ----------------

__global__ void __launch_bounds__(NT, 1)
fastmax_bf16x2_kernel(float* __restrict__ out)
{
    extern __shared__ float sm[];
    uint32_t smb;
    asm("{.reg .u64 t; cvta.to.shared.u64 t, %1; cvt.u32.u64 %0, t;}"
        : "=r"(smb) : "l"(sm));

    const int tid  = threadIdx.x;
    const int lane = tid & 31;
    const int wid  = tid >> 5;
    const int g    = lane >> 2;
    const int t4   = lane & 3;
    const int wm   = wid & 3;
    const int wn   = wid >> 2;

    // 144-CTA balanced schedule: total tiles per CTA <= 32, single wave.
    const int bx = blockIdx.x;
    int h, ib0, ib1, npass;
    if (bx < 32) {
        h = bx >> 2; ib0 = 28 + (bx & 3); ib1 = 0; npass = 1;   // 29..32 tiles
    } else {
        int c = bx - 32;             // [0,112)
        h = c / 14;
        int p = c % 14;
        ib0 = 27 - p; ib1 = p; npass = 2;                        // 29 tiles
    }

    float* sps = sm + RING;
    const int prow0 = 16 * wm + g;
    float* psrow0 = sps + prow0 * PSTR;
    float* psrow1 = sps + (prow0 + 8) * PSTR;
    float* op = out + (size_t)h * N * D;

    #pragma unroll 1
    for (int pass = 0; pass < npass; pass++) {
        const int ib = pass ? ib1 : ib0;
        const int i0 = ib * 64;

        // Q fragments (persistent, registers)
        uint32_t qa1[4][4], qa2[4][4];
        #pragma unroll
        for (int c = 0; c < 4; c++) {
            const float4* src = &g_qpack[(((size_t)(h * 128 + ib * 4 + wm) * 4 + c) * 32 + lane) * 2];
            float4 A1 = src[0], A2 = src[1];
            qa1[c][0] = __float_as_uint(A1.x); qa1[c][1] = __float_as_uint(A1.y);
            qa1[c][2] = __float_as_uint(A1.z); qa1[c][3] = __float_as_uint(A1.w);
            qa2[c][0] = __float_as_uint(A2.x); qa2[c][1] = __float_as_uint(A2.y);
            qa2[c][2] = __float_as_uint(A2.z); qa2[c][3] = __float_as_uint(A2.w);
        }

        float oacc[8][4];
        #pragma unroll
        for (int nt = 0; nt < 8; nt++)
            #pragma unroll
            for (int c = 0; c < 4; c++) oacc[nt][c] = 0.f;
        float den0 = 0.f, den1 = 0.f;

        // prefetch tile 0 into buf 0
        {
            const float4* gk = g_kpack + (size_t)(h * 32 + ib) * 1024;
            const float4* gr = g_rpack;
            const float4* gv = ((const float4*)g_vpack) + (size_t)(h * 32 + ib) * 1024;
            for (int t = tid; t < 1024; t += NT) {
                cp16(smb + t * 16,         gk + t);
                cp16(smb + 16384 + t * 16, gr + t);
                cp16(smb + 32768 + t * 16, gv + t);
            }
            asm volatile("cp.async.commit_group;" ::: "memory");
        }

        for (int m = 0; m <= ib; m++) {
            asm volatile("cp.async.wait_group 0;" ::: "memory");
            __syncthreads();                        // buf[m&1] ready everywhere

            if (m < ib) {                           // prefetch next into other buf
                const int jb = ib - m - 1;
                const float4* gk = g_kpack + (size_t)(h * 32 + jb) * 1024;
                const float4* gr = g_rpack + (size_t)(m + 1) * 1024;
                const float4* gv = ((const float4*)g_vpack) + (size_t)(h * 32 + jb) * 1024;
                uint32_t sb = smb + ((m + 1) & 1) * (BUFSZ * 4);
                for (int t = tid; t < 1024; t += NT) {
                    cp16(sb + t * 16,         gk + t);
                    cp16(sb + 16384 + t * 16, gr + t);
                    cp16(sb + 32768 + t * 16, gv + t);
                }
                asm volatile("cp.async.commit_group;" ::: "memory");
            }

            const uint4* kb4 = (const uint4*)(sm + (m & 1) * BUFSZ);
            const uint4* rb4 = kb4 + 1024;
            const uint2* vb2 = (const uint2*)(sm + (m & 1) * BUFSZ + 8192);

            // ---- S = QK^T, P = QR^T  (bf16x2: hh + lh + hl) ----
            float sacc[2][4], pacc[2][4];
            #pragma unroll
            for (int nt = 0; nt < 2; nt++)
                #pragma unroll
                for (int c = 0; c < 4; c++) { sacc[nt][c] = 0.f; pacc[nt][c] = 0.f; }

            #pragma unroll
            for (int c = 0; c < 4; c++) {
                #pragma unroll
                for (int nt = 0; nt < 2; nt++) {
                    int fi = (c * 64 + 16 * wn + 8 * nt + g) * 4 + t4;
                    uint4 kf = kb4[fi];
                    mma16(sacc[nt], qa1[c], kf.x, kf.y);
                    mma16(sacc[nt], qa2[c], kf.x, kf.y);
                    mma16(sacc[nt], qa1[c], kf.z, kf.w);
                    uint4 rf = rb4[fi];
                    mma16(pacc[nt], qa1[c], rf.x, rf.y);
                    mma16(pacc[nt], qa2[c], rf.x, rf.y);
                    mma16(pacc[nt], qa1[c], rf.z, rf.w);
                }
            }

            // ---- P-new into wm-partitioned 128-slot ring ----
            {
                const int bslot = (64 * m) & 127;
                #pragma unroll
                for (int nt = 0; nt < 2; nt++) {
                    int dl = 16 * wn + 8 * nt + 2 * t4;
                    *(float2*)&psrow0[bslot + dl] = make_float2(pacc[nt][0], pacc[nt][1]);
                    *(float2*)&psrow1[bslot + dl] = make_float2(pacc[nt][2], pacc[nt][3]);
                }
            }
            asm volatile("bar.sync %0, %1;" :: "r"(1 + wm), "r"(128) : "memory");

            // ---- s += P gather; w = 1+s+s^2/2; causal; den from rounded w ----
            uint32_t wt[2][4];
            #pragma unroll
            for (int nt = 0; nt < 2; nt++) {
                int colb = 16 * wn + 8 * nt + 2 * t4;
                #pragma unroll
                for (int c = 0; c < 4; c++) {
                    int row_l = prow0 + ((c >> 1) << 3);
                    int col_l = colb + (c & 1);
                    unsigned slot = (unsigned)(64 * m + row_l - col_l) & 127u;
                    float s = sacc[nt][c] + sps[row_l * PSTR + slot];
                    float w = fmaf(s, fmaf(s, 0.5f, 1.0f), 1.0f);
                    if (m == 0 && col_l > row_l) w = 0.0f;
                    uint32_t wu = tf32r(w);
                    wt[nt][c] = wu;
                    if (c < 2) den0 += __uint_as_float(wu);
                    else       den1 += __uint_as_float(wu);
                }
            }

            // ---- O += W x V (A-frags via shuffles; V single tf32) ----
            #pragma unroll
            for (int kk = 0; kk < 2; kk++) {
                const int src = 4 * g + (t4 >> 1);
                uint32_t v00  = __shfl_sync(0xffffffffu, wt[kk][0], src);
                uint32_t v01  = __shfl_sync(0xffffffffu, wt[kk][1], src);
                uint32_t v20  = __shfl_sync(0xffffffffu, wt[kk][2], src);
                uint32_t v21  = __shfl_sync(0xffffffffu, wt[kk][3], src);
                uint32_t v00b = __shfl_sync(0xffffffffu, wt[kk][0], src + 2);
                uint32_t v01b = __shfl_sync(0xffffffffu, wt[kk][1], src + 2);
                uint32_t v20b = __shfl_sync(0xffffffffu, wt[kk][2], src + 2);
                uint32_t v21b = __shfl_sync(0xffffffffu, wt[kk][3], src + 2);
                uint32_t a[4];
                const bool odd = (t4 & 1);
                a[0] = odd ? v01  : v00;
                a[1] = odd ? v21  : v20;
                a[2] = odd ? v01b : v00b;
                a[3] = odd ? v21b : v20b;
                const int cj = 2 * wn + kk;
                #pragma unroll
                for (int nt = 0; nt < 8; nt++) {
                    uint2 vf = vb2[(cj * 64 + 8 * nt + g) * 4 + t4];
                    mma8(oacc[nt], a, vf.x, vf.y);
                }
            }
        }

        // ---- epilogue: den lane-reduce, combine 4 wn partials, write ----
        den0 += __shfl_xor_sync(0xffffffffu, den0, 1);
        den0 += __shfl_xor_sync(0xffffffffu, den0, 2);
        den1 += __shfl_xor_sync(0xffffffffu, den1, 1);
        den1 += __shfl_xor_sync(0xffffffffu, den1, 2);

        __syncthreads();                 // all smem reads of final tile done
        float* ob1  = sm;                // scratch over buffer region
        float* ob2  = sm + 4352;
        float* ob3  = sm + 8704;
        float* denb = sm + DENB;

        if (wn > 0) {
            float* ob = (wn == 1) ? ob1 : (wn == 2) ? ob2 : ob3;
            #pragma unroll
            for (int nt = 0; nt < 8; nt++) {
                int dcol = 8 * nt + 2 * t4;
                *(float2*)&ob[prow0 * KSTR + dcol]       = make_float2(oacc[nt][0], oacc[nt][1]);
                *(float2*)&ob[(prow0 + 8) * KSTR + dcol] = make_float2(oacc[nt][2], oacc[nt][3]);
            }
            if (t4 == 0) {
                denb[prow0 * 4 + wn]       = den0;
                denb[(prow0 + 8) * 4 + wn] = den1;
            }
        }
        __syncthreads();
        if (wn == 0) {
            float d0 = den0 + denb[prow0 * 4 + 1] + denb[prow0 * 4 + 2] + denb[prow0 * 4 + 3];
            float d1 = den1 + denb[(prow0 + 8) * 4 + 1] + denb[(prow0 + 8) * 4 + 2]
                            + denb[(prow0 + 8) * 4 + 3];
            float inv0 = 1.0f / d0;
            float inv1 = 1.0f / d1;
            #pragma unroll
            for (int nt = 0; nt < 8; nt++) {
                int dcol = 8 * nt + 2 * t4;
                float2 p1 = *(const float2*)&ob1[prow0 * KSTR + dcol];
                float2 p2 = *(const float2*)&ob2[prow0 * KSTR + dcol];
                float2 p3 = *(const float2*)&ob3[prow0 * KSTR + dcol];
                float2 q1 = *(const float2*)&ob1[(prow0 + 8) * KSTR + dcol];
                float2 q2 = *(const float2*)&ob2[(prow0 + 8) * KSTR + dcol];
                float2 q3 = *(const float2*)&ob3[(prow0 + 8) * KSTR + dcol];
                float2 o0 = make_float2((oacc[nt][0] + p1.x + p2.x + p3.x) * inv0,
                                        (oacc[nt][1] + p1.y + p2.y + p3.y) * inv0);
                float2 o1 = make_float2((oacc[nt][2] + q1.x + q2.x + q3.x) * inv1,
                                        (oacc[nt][3] + q1.y + q2.y + q3.y) * inv1);
                *(float2*)&op[(size_t)(i0 + prow0) * D + dcol]     = o0;
                *(float2*)&op[(size_t)(i0 + prow0 + 8) * D + dcol] = o1;
            }
        }
        __syncthreads();                 // scratch free before next pass prefetch
    }
}

extern "C" void kernel_launch(void* const* d_in, const int* in_sizes, int n_in,
                              void* d_out, int out_size)
{
    (void)in_sizes; (void)n_in; (void)out_size;
    const float* q   = (const float*)d_in[0];
    const float* k   = (const float*)d_in[1];
    const float* v   = (const float*)d_in[2];
    const float* rpe = (const float*)d_in[3];
    float* out = (float*)d_out;

    pp_fused<<<3712, 256>>>(q, k, v, rpe);

    cudaFuncSetAttribute(fastmax_bf16x2_kernel,
                         cudaFuncAttributeMaxDynamicSharedMemorySize, SMEM_BYTES);
    fastmax_bf16x2_kernel<<<144, NT, SMEM_BYTES>>>(out);
}